// round 13
// baseline (speedup 1.0000x reference)
#include <cuda_runtime.h>
#include <cuda_bf16.h>
#include <cstdint>

// ---------------- problem constants ----------------
#define NN      50000
#define EE      800000
#define IN_DIM  128
#define HID     64
#define HEADS   4
#define FW      256          // HEADS*HID
#define OUT_DIM 40
#define NEG     0.2f

// ---------------- device scratch (no allocs allowed) ----------------
__device__ __align__(16) float g_h0[(size_t)NN * HID];        // 12.8 MB
__device__ __align__(16) float g_h [(size_t)NN * FW];         // 51.2 MB
__device__ __align__(16) float g_go[(size_t)NN * FW];         // 51.2 MB relu(gat_out)
__device__ __align__(16) float g_asrc[(size_t)NN * 4];
__device__ __align__(16) float g_adst[(size_t)NN * 4];
__device__ int g_cnt[NN + 1];
__device__ int g_cur[NN + 1];
__device__ int g_off[NN + 1];
__device__ int g_csr[EE];
__device__ int g_src[EE];
__device__ int g_dst[EE];
__device__ int g_ts [NN];
__device__ int g_is64;

__device__ __forceinline__ float lrelu(float v) { return v > 0.f ? v : NEG * v; }

// ---- tf32 helpers ----
__device__ __forceinline__ uint32_t f2tf(float f) {
    uint32_t u; asm("cvt.rna.tf32.f32 %0, %1;" : "=r"(u) : "f"(f)); return u;
}
__device__ __forceinline__ void mma_tf32(float* c,
                                         uint32_t a0, uint32_t a1, uint32_t a2, uint32_t a3,
                                         uint32_t b0, uint32_t b1) {
    asm volatile(
        "mma.sync.aligned.m16n8k8.row.col.f32.tf32.tf32.f32 "
        "{%0,%1,%2,%3}, {%4,%5,%6,%7}, {%8,%9}, {%0,%1,%2,%3};"
        : "+f"(c[0]), "+f"(c[1]), "+f"(c[2]), "+f"(c[3])
        : "r"(a0), "r"(a1), "r"(a2), "r"(a3), "r"(b0), "r"(b1));
}

// ---------------- A. zero counters + dtype detection ----------------
__global__ void k_init(const int* __restrict__ ei_raw, int N) {
    int i = blockIdx.x * blockDim.x + threadIdx.x;
    if (i < N) { g_cnt[i] = 0; g_cur[i] = 0; }
    if (blockIdx.x == 0 && threadIdx.x == 0) {
        int allzero = 1;
        for (int k = 1; k < 256; k += 2)
            if (ei_raw[k] != 0) { allzero = 0; break; }
        g_is64 = allzero;
    }
}

// ---------------- B. convert edges + histogram + timesteps ----------------
__global__ void k_cvt(const void* __restrict__ ei, const void* __restrict__ ts,
                      int E, int N) {
    int e = blockIdx.x * blockDim.x + threadIdx.x;
    int is64 = g_is64;
    if (e < E) {
        int s, d;
        if (is64) {
            const long long* p = (const long long*)ei;
            s = (int)p[e];
            d = (int)p[(size_t)E + e];
        } else {
            const int* p = (const int*)ei;
            s = p[e];
            d = p[(size_t)E + e];
        }
        g_src[e] = s;
        g_dst[e] = d;
        atomicAdd(&g_cnt[d], 1);
    }
    if (e < N)
        g_ts[e] = is64 ? (int)((const long long*)ts)[e] : ((const int*)ts)[e];
}

// ---------------- 1. h0 = relu(x @ W_proj + b) + temb[ts]   [N,128]x[128,64]
__global__ __launch_bounds__(256) void k_proj(const float* __restrict__ x,
                                              const float* __restrict__ Wp,
                                              const float* __restrict__ bp,
                                              const float* __restrict__ temb,
                                              int N) {
    extern __shared__ float sm[];
    float* Ws = sm;                 // 128*64
    float* Xs = sm + IN_DIM * HID;  // 64*128
    int t = threadIdx.x;
    int row0 = blockIdx.x * 64;
    #pragma unroll
    for (int i = 0; i < 8; i++)
        ((float4*)Ws)[t + 256 * i] = ((const float4*)Wp)[t + 256 * i];
    #pragma unroll
    for (int i = 0; i < 8; i++) {
        int lin = t + 256 * i;
        int r = lin >> 5, c4 = lin & 31;
        float4 v = make_float4(0.f, 0.f, 0.f, 0.f);
        if (row0 + r < N) v = ((const float4*)x)[(size_t)(row0 + r) * 32 + c4];
        ((float4*)Xs)[lin] = v;
    }
    __syncthreads();
    int warp = t >> 5, lane = t & 31;
    float acc0[8] = {0}, acc1[8] = {0};
    #pragma unroll 4
    for (int k = 0; k < IN_DIM; k++) {
        float w0 = Ws[k * HID + lane];
        float w1 = Ws[k * HID + lane + 32];
        #pragma unroll
        for (int r = 0; r < 8; r++) {
            float xv = Xs[(warp * 8 + r) * IN_DIM + k];
            acc0[r] += xv * w0;
            acc1[r] += xv * w1;
        }
    }
    float b0 = bp[lane], b1 = bp[lane + 32];
    #pragma unroll
    for (int r = 0; r < 8; r++) {
        int row = row0 + warp * 8 + r;
        if (row < N) {
            int tt = g_ts[row];
            float v0 = fmaxf(acc0[r] + b0, 0.f) + temb[tt * HID + lane];
            float v1 = fmaxf(acc1[r] + b1, 0.f) + temb[tt * HID + lane + 32];
            g_h0[(size_t)row * HID + lane]      = v0;
            g_h0[(size_t)row * HID + lane + 32] = v1;
        }
    }
}

// ---------------- 2. h = h0 @ W_gat  via mma.sync tf32 (split-precision, ~fp32 exact)
//                    + fused attention logits from folded weights
#define APAD 76    // 76 % 32 == 12 -> A-frag banks 12*g+tg all distinct
#define BPAD 264   // 264 % 32 == 8 -> B-frag banks 8*tg+g all distinct
__global__ __launch_bounds__(256, 2) void k_lin(const float* __restrict__ Wg,
                                                const float* __restrict__ att_s,
                                                const float* __restrict__ att_d,
                                                int N) {
    extern __shared__ float sm[];
    float* As    = sm;                    // [64][APAD] h0 tile
    float* Bs    = As + 64 * APAD;        // [64][BPAD] Wg (k-major rows)
    float* satt  = Bs + 64 * BPAD;        // 512: att_s | att_d
    float* sfold = satt + 512;            // 512: folded weights [k][h][s/d]
    int t = threadIdx.x;
    int row0 = blockIdx.x * 64;

    // load Wg [64][256] into padded Bs
    for (int i = t; i < 64 * 64; i += 256) {       // 4096 float4
        int k = i >> 6, c4 = i & 63;
        float4 v = ((const float4*)Wg)[k * 64 + c4];
        *(float4*)(Bs + k * BPAD + c4 * 4) = v;
    }
    // load h0 tile [64][64] into padded As (zero-pad OOB rows)
    for (int i = t; i < 64 * 16; i += 256) {       // 1024 float4
        int r = i >> 4, c4 = i & 15;
        float4 v = make_float4(0.f, 0.f, 0.f, 0.f);
        if (row0 + r < N) v = ((const float4*)g_h0)[(size_t)(row0 + r) * 16 + c4];
        *(float4*)(As + r * APAD + c4 * 4) = v;
    }
    satt[t]       = att_s[t];
    satt[256 + t] = att_d[t];
    __syncthreads();

    int wid = t >> 5, lane = t & 31;
    int warpM = wid >> 1, nhalf = wid & 1;     // 4 M-groups x 2 N-halves
    int g = lane >> 2, tg = lane & 3;

    float C[16][4];
    #pragma unroll
    for (int nt = 0; nt < 16; nt++)
        #pragma unroll
        for (int j = 0; j < 4; j++) C[nt][j] = 0.f;

    #pragma unroll 2
    for (int ks = 0; ks < 8; ks++) {
        const float* ap = As + (warpM * 16 + g) * APAD + ks * 8 + tg;
        float af0 = ap[0],          af2 = ap[4];
        float af1 = ap[8 * APAD],   af3 = ap[8 * APAD + 4];
        uint32_t ah0 = f2tf(af0), ah1 = f2tf(af1), ah2 = f2tf(af2), ah3 = f2tf(af3);
        uint32_t al0 = f2tf(af0 - __uint_as_float(ah0));
        uint32_t al1 = f2tf(af1 - __uint_as_float(ah1));
        uint32_t al2 = f2tf(af2 - __uint_as_float(ah2));
        uint32_t al3 = f2tf(af3 - __uint_as_float(ah3));
        #pragma unroll
        for (int nt = 0; nt < 16; nt++) {
            const float* bp = Bs + (ks * 8 + tg) * BPAD + nhalf * 128 + nt * 8 + g;
            float bf0 = bp[0], bf1 = bp[4 * BPAD];
            uint32_t bh0 = f2tf(bf0), bh1 = f2tf(bf1);
            uint32_t bl0 = f2tf(bf0 - __uint_as_float(bh0));
            uint32_t bl1 = f2tf(bf1 - __uint_as_float(bh1));
            mma_tf32(C[nt], ah0, ah1, ah2, ah3, bh0, bh1);
            mma_tf32(C[nt], ah0, ah1, ah2, ah3, bl0, bl1);
            mma_tf32(C[nt], al0, al1, al2, al3, bh0, bh1);
        }
    }

    // store C -> g_h
    {
        int r0 = row0 + warpM * 16 + g;
        int r1 = r0 + 8;
        #pragma unroll
        for (int nt = 0; nt < 16; nt++) {
            int col = nhalf * 128 + nt * 8 + 2 * tg;
            if (r0 < N) *(float2*)(g_h + (size_t)r0 * FW + col) = make_float2(C[nt][0], C[nt][1]);
            if (r1 < N) *(float2*)(g_h + (size_t)r1 * FW + col) = make_float2(C[nt][2], C[nt][3]);
        }
    }

    // fold: sfold[k*8 + h*2 + sd] = sum_c Wg[k][h*64+c] * att_{s,d}[h][c]
    for (int o = t; o < 512; o += 256) {
        int k = o >> 3, hh = (o >> 1) & 3, sd = o & 1;
        const float* wrow = Bs + k * BPAD + hh * 64;
        const float* av   = satt + sd * 256 + hh * 64;
        float s = 0.f;
        #pragma unroll 8
        for (int c = 0; c < 64; c++) s += wrow[c] * av[c];
        sfold[o] = s;
    }
    __syncthreads();
    // logits: a[row][h] = sum_k h0[row][k] * fold[k][h]
    for (int o = t; o < 512; o += 256) {
        int row = o >> 3, hh = (o >> 1) & 3, sd = o & 1;
        if (row0 + row < N) {
            const float* hr = As + row * APAD;
            float s = 0.f;
            #pragma unroll 8
            for (int k = 0; k < 64; k++) s += hr[k] * sfold[k * 8 + hh * 2 + sd];
            (sd ? g_adst : g_asrc)[(size_t)(row0 + row) * 4 + hh] = s;
        }
    }
}

// ---------------- 4. CSR by destination ----------------
__global__ void k_scan(int N) {
    __shared__ int sp[1024];
    int t = threadIdx.x;
    int C = (N + 1023) / 1024;
    int lo = t * C, hi = lo + C; if (hi > N) hi = N; if (lo > N) lo = N;
    int s = 0;
    for (int i = lo; i < hi; i++) s += g_cnt[i];
    sp[t] = s;
    __syncthreads();
    for (int off = 1; off < 1024; off <<= 1) {
        int v = (t >= off) ? sp[t - off] : 0;
        __syncthreads();
        sp[t] += v;
        __syncthreads();
    }
    int run = sp[t] - s;      // exclusive prefix
    for (int i = lo; i < hi; i++) { g_off[i] = run; run += g_cnt[i]; }
    if (t == 1023) g_off[N] = run;
}
__global__ void k_fill(int E) {
    int e = blockIdx.x * blockDim.x + threadIdx.x;
    if (e < E) {
        int d = g_dst[e];
        int pos = g_off[d] + atomicAdd(&g_cur[d], 1);
        g_csr[pos] = g_src[e];
    }
}

// ---------------- 5. per-dst online-softmax gather -> g_go (relu'd, + b_gat) ----------------
__global__ __launch_bounds__(256) void k_gat(const float* __restrict__ bg, int N) {
    int t = threadIdx.x;
    int warp = t >> 5, lane = t & 31;
    int n = blockIdx.x * 8 + warp;
    if (n >= N) return;
    const float4* asrc4 = (const float4*)g_asrc;
    float4 ad = ((const float4*)g_adst)[n];
    float4 as = asrc4[n];
    // self-loop initializes online softmax (p = exp(0) = 1)
    float m0 = lrelu(as.x + ad.x), m1 = lrelu(as.y + ad.y);
    float m2 = lrelu(as.z + ad.z), m3 = lrelu(as.w + ad.w);
    float d0 = 1.f, d1 = 1.f, d2 = 1.f, d3 = 1.f;
    const float4* hself = (const float4*)(g_h + (size_t)n * FW);
    float4 acc0 = hself[lane];
    float4 acc1 = hself[lane + 32];
    bool lo = lane < 16;

    int beg = g_off[n], end = g_off[n + 1];
    if (beg < end) {
        int last = end - 1;
        int s0 = g_csr[beg];
        int i1 = beg + 1 < last ? beg + 1 : last;
        int s1 = g_csr[i1];
        float4 a = asrc4[s0];
        for (int i = beg; i < end; i++) {
            int i2 = i + 2 < last ? i + 2 : last;
            int s2 = g_csr[i2];                 // 2-ahead (clamped)
            float4 aN = asrc4[s1];              // 1-ahead
            const float4* hq = (const float4*)(g_h + (size_t)s0 * FW);
            float4 hA = hq[lane];
            float4 hB = hq[lane + 32];
            float e0 = lrelu(a.x + ad.x), e1 = lrelu(a.y + ad.y);
            float e2 = lrelu(a.z + ad.z), e3 = lrelu(a.w + ad.w);
            if (e0 > m0 || e1 > m1 || e2 > m2 || e3 > m3) {   // warp-uniform
                float n0 = fmaxf(m0, e0), n1 = fmaxf(m1, e1);
                float n2 = fmaxf(m2, e2), n3 = fmaxf(m3, e3);
                float s0f = __expf(m0 - n0), s1f = __expf(m1 - n1);
                float s2f = __expf(m2 - n2), s3f = __expf(m3 - n3);
                d0 *= s0f; d1 *= s1f; d2 *= s2f; d3 *= s3f;
                float sa = lo ? s0f : s1f, sb = lo ? s2f : s3f;
                acc0.x *= sa; acc0.y *= sa; acc0.z *= sa; acc0.w *= sa;
                acc1.x *= sb; acc1.y *= sb; acc1.z *= sb; acc1.w *= sb;
                m0 = n0; m1 = n1; m2 = n2; m3 = n3;
            }
            float p0 = __expf(e0 - m0), p1 = __expf(e1 - m1);
            float p2 = __expf(e2 - m2), p3 = __expf(e3 - m3);
            d0 += p0; d1 += p1; d2 += p2; d3 += p3;
            float pa = lo ? p0 : p1, pb = lo ? p2 : p3;
            acc0.x += pa * hA.x; acc0.y += pa * hA.y; acc0.z += pa * hA.z; acc0.w += pa * hA.w;
            acc1.x += pb * hB.x; acc1.y += pb * hB.y; acc1.z += pb * hB.z; acc1.w += pb * hB.w;
            s0 = s1; s1 = s2; a = aN;
        }
    }
    float r0 = 1.f / (d0 + 1e-16f), r1 = 1.f / (d1 + 1e-16f);
    float r2 = 1.f / (d2 + 1e-16f), r3 = 1.f / (d3 + 1e-16f);
    float ra = lo ? r0 : r1, rb = lo ? r2 : r3;
    float4 bgA = ((const float4*)bg)[lane];
    float4 bgB = ((const float4*)bg)[lane + 32];
    float4 o0, o1;
    o0.x = fmaxf(acc0.x * ra + bgA.x, 0.f);
    o0.y = fmaxf(acc0.y * ra + bgA.y, 0.f);
    o0.z = fmaxf(acc0.z * ra + bgA.z, 0.f);
    o0.w = fmaxf(acc0.w * ra + bgA.w, 0.f);
    o1.x = fmaxf(acc1.x * rb + bgB.x, 0.f);
    o1.y = fmaxf(acc1.y * rb + bgB.y, 0.f);
    o1.z = fmaxf(acc1.z * rb + bgB.z, 0.f);
    o1.w = fmaxf(acc1.w * rb + bgB.w, 0.f);
    ((float4*)(g_go + (size_t)n * FW))[lane]      = o0;
    ((float4*)(g_go + (size_t)n * FW))[lane + 32] = o1;
}

// ---------------- 6. classifier GEMM: out = g_go @ Wc + bc  [N,256]x[256,40]
#define KP 260   // padded K stride (bank-spread, divisible by 4)
__global__ __launch_bounds__(256, 2) void k_cls(const float* __restrict__ Wc,
                                                const float* __restrict__ bc,
                                                float* __restrict__ out, int N) {
    extern __shared__ float sm[];
    float* sW = sm;               // [40][KP] transposed Wc
    float* sA = sm + 40 * KP;     // [64][KP]
    int t = threadIdx.x;
    int row0 = blockIdx.x * 64;
    for (int idx = t; idx < FW * OUT_DIM; idx += 256) {
        int k = idx / OUT_DIM, c = idx % OUT_DIM;
        sW[c * KP + k] = Wc[idx];
    }
    #pragma unroll
    for (int i = 0; i < 16; i++) {
        int lin = t + 256 * i;          // 4096 float4 slots
        int r = lin >> 6, c4 = lin & 63;
        float4 v = make_float4(0.f, 0.f, 0.f, 0.f);
        if (row0 + r < N) v = ((const float4*)g_go)[(size_t)(row0 + r) * 64 + c4];
        *(float4*)(sA + r * KP + c4 * 4) = v;
    }
    __syncthreads();
    int colg = t & 7;        // 8 column groups x 5 cols
    int rp   = t >> 3;       // 32 row pairs
    const float* a0p = sA + (rp * 2) * KP;
    const float* a1p = sA + (rp * 2 + 1) * KP;
    float acc0[5] = {0}, acc1[5] = {0};
    #pragma unroll 4
    for (int k4 = 0; k4 < 64; k4++) {
        float4 a0 = ((const float4*)a0p)[k4];
        float4 a1 = ((const float4*)a1p)[k4];
        #pragma unroll
        for (int i = 0; i < 5; i++) {
            float4 w = ((const float4*)(sW + (colg * 5 + i) * KP))[k4];
            acc0[i] += a0.x * w.x + a0.y * w.y + a0.z * w.z + a0.w * w.w;
            acc1[i] += a1.x * w.x + a1.y * w.y + a1.z * w.z + a1.w * w.w;
        }
    }
    int r0 = row0 + rp * 2, r1 = r0 + 1;
    #pragma unroll
    for (int i = 0; i < 5; i++) {
        int c = colg * 5 + i;
        float b = bc[c];
        if (r0 < N) out[(size_t)r0 * OUT_DIM + c] = acc0[i] + b;
        if (r1 < N) out[(size_t)r1 * OUT_DIM + c] = acc1[i] + b;
    }
}

// ---------------- launch ----------------
extern "C" void kernel_launch(void* const* d_in, const int* in_sizes, int n_in,
                              void* d_out, int out_size) {
    const float* x    = (const float*)d_in[0];
    const void*  ei   = d_in[1];
    const void*  ts   = d_in[2];
    const float* Wp   = (const float*)d_in[3];
    const float* bp   = (const float*)d_in[4];
    const float* temb = (const float*)d_in[5];
    const float* Wg   = (const float*)d_in[6];
    const float* atts = (const float*)d_in[7];
    const float* attd = (const float*)d_in[8];
    const float* bg   = (const float*)d_in[9];
    const float* Wc   = (const float*)d_in[10];
    const float* bc   = (const float*)d_in[11];
    float* out = (float*)d_out;

    int N = in_sizes[0] / IN_DIM;   // 50000
    int E = in_sizes[1] / 2;        // 800000

    size_t sm_proj = (size_t)(IN_DIM * HID + 64 * IN_DIM) * 4;          // 64 KB
    size_t sm_lin  = (size_t)(64 * APAD + 64 * BPAD + 512 + 512) * 4;   // ~89 KB
    size_t sm_cls  = (size_t)(40 * KP + 64 * KP) * 4;                   // ~106 KB
    cudaFuncSetAttribute(k_proj, cudaFuncAttributeMaxDynamicSharedMemorySize, (int)sm_proj);
    cudaFuncSetAttribute(k_lin,  cudaFuncAttributeMaxDynamicSharedMemorySize, (int)sm_lin);
    cudaFuncSetAttribute(k_cls,  cudaFuncAttributeMaxDynamicSharedMemorySize, (int)sm_cls);

    k_init<<<(N + 255) / 256, 256>>>((const int*)ei, N);
    k_cvt <<<(E + 255) / 256, 256>>>(ei, ts, E, N);
    k_proj<<<(N + 63) / 64, 256, sm_proj>>>(x, Wp, bp, temb, N);
    k_lin <<<(N + 63) / 64, 256, sm_lin>>>(Wg, atts, attd, N);
    k_scan<<<1, 1024>>>(N);
    k_fill<<<(E + 255) / 256, 256>>>(E);
    k_gat <<<(N + 7) / 8, 256>>>(bg, N);
    k_cls <<<(N + 63) / 64, 256, sm_cls>>>(Wc, bc, out, N);
}